// round 16
// baseline (speedup 1.0000x reference)
#include <cuda_runtime.h>

#define E_EDGES 65536
#define NGO 4096
#define B_SZ 16
#define G_SZ 1024
#define BKT_CAP 96

// ---------------- scratch (__device__ globals; no allocs allowed) ----------------
__device__ float g_xcat[B_SZ * G_SZ];        // [B][G] partial sums; zeroed by k_readout for next run
__device__ float g_h[NGO * 96];              // [N][B][6]
__device__ float g_hn[NGO * 128];            // [N][B][2][4]
__device__ float g_si[NGO * 32];             // [N][B][2]
__device__ float g_sj[NGO * 32];             // [N][B][2]
__device__ float g_o[B_SZ * 16384];          // [B][C*N]  (lrelu applied)
__device__ float g_wpk[NGO * 6 * 128];       // packed masked weights [grp][6][128]
__device__ int   g_idxcnt[NGO];              // nnz count per mask group
__device__ int   g_idxbuf[NGO * 1024];       // nnz gene indices per mask group
__device__ int   g_cnt[NGO];                 // zero-init; k_readout role re-zeroes each run
__device__ int   g_bkt[NGO * BKT_CAP];       // direct CSR buckets: src per slot

__device__ __forceinline__ float lrelu(float x, float s) { return x >= 0.f ? x : s * x; }

// ---------------- L1: mega-kernel — prep + edge-bucket + subnet (short roles first) ----
// blocks [0,512): prep; [512,576): edge bucket; [576,2624): subnet
__global__ __launch_bounds__(256) void k_main1(const float* __restrict__ x,
                                               const float* __restrict__ Wsub,
                                               const float* __restrict__ fw,
                                               const float* __restrict__ mr,
                                               const int* __restrict__ ei) {
    int bid = blockIdx.x, tid = threadIdx.x;
    if (bid < 512) {
        // ---- prep: warp per group — compact mask row, pack 6 weight rows ----
        __shared__ int s_idx[8][128];
        int w = tid >> 5, lane = tid & 31;
        int grp = bid * 8 + w;
        const float* row = mr + (size_t)grp * 6144;   // rows 6g..6g+5 identical
        int* gout = g_idxbuf + grp * 1024;
        int cnt = 0;
#pragma unroll 4
        for (int c = 0; c < 32; c++) {
            float v = row[c * 32 + lane];
            unsigned ball = __ballot_sync(0xffffffffu, v != 0.f);
            if (v != 0.f) {
                int p = cnt + __popc(ball & ((1u << lane) - 1u));
                gout[p] = c * 32 + lane;
                if (p < 128) s_idx[w][p] = c * 32 + lane;
            }
            cnt += __popc(ball);
        }
        if (lane == 0) g_idxcnt[grp] = cnt;
        __syncwarp();
        const float* wb = fw + (size_t)grp * 6144;
        float* pk = g_wpk + grp * 768;
        int cend = min(cnt, 128);
        for (int k = lane; k < cend; k += 32) {
            int g = s_idx[w][k];
#pragma unroll
            for (int r = 0; r < 6; r++) pk[r * 128 + k] = wb[r * 1024 + g];
        }
    } else if (bid < 576) {
        // ---- edge bucket: local int64/int32 detect + direct CSR build ----
        int ok = (ei[2 * tid + 1] == 0);
        int ef = __syncthreads_and(ok);
        int e0 = (bid - 512) * 1024;
#pragma unroll
        for (int it = 0; it < 4; it++) {
            int e = e0 + it * 256 + tid;
            int dst = ef ? ei[2 * (E_EDGES + e)] : ei[E_EDGES + e];
            int src = ef ? ei[2 * e] : ei[e];
            int pos = atomicAdd(&g_cnt[dst], 1);
            if (pos < BKT_CAP) g_bkt[dst * BKT_CAP + pos] = src;  // P(overflow) ~ 1e-40
        }
    } else {
        // ---- subnet: 4 genes x 64 t-rows x 8 b per block ----
        int bs = bid - 576;
        int bx = bs & 255, by = (bs >> 8) & 3, bz = bs >> 10;
        int g0 = bx * 4;
        int c = tid & 15, tr = tid >> 4;
        int gene = g0 + (c >> 2), pq = c & 3;
        int b0 = bz * 8;
        const float4* x4 = (const float4*)x;
        const float4* w4 = (const float4*)Wsub;
        float acc[8];
#pragma unroll
        for (int b = 0; b < 8; b++) acc[b] = 0.f;
        int tbase = by * 64;
#pragma unroll 1
        for (int pass = 0; pass < 4; pass++) {
            int t = tbase + pass * 16 + tr;
            float4 w = w4[gene * 1024 + t * 4 + pq];
            int xoff = t * 4096 + g0 * 4 + c;
#pragma unroll
            for (int b = 0; b < 8; b++) {
                float4 xv = x4[(b0 + b) * 1048576 + xoff];
                acc[b] += w.x * xv.x + w.y * xv.y + w.z * xv.z + w.w * xv.w;
            }
        }
        __shared__ float red[8][4][8];
        int lane = tid & 31, wid = tid >> 5;
#pragma unroll
        for (int b = 0; b < 8; b++) {
            float v = acc[b];
            v += __shfl_xor_sync(0xffffffffu, v, 16);
            v += __shfl_xor_sync(0xffffffffu, v, 2);
            v += __shfl_xor_sync(0xffffffffu, v, 1);
            if ((lane & 3) == 0 && lane < 16) red[wid][lane >> 2][b] = v;
        }
        __syncthreads();
        if (tid < 32) {
            int gl = tid >> 3, b = tid & 7;
            float s = 0.f;
#pragma unroll
            for (int w2 = 0; w2 < 8; w2++) s += red[w2][gl][b];
            atomicAdd(&g_xcat[(b0 + b) * G_SZ + g0 + gl], s);
        }
    }
}

// ---------------- L2: packed-sparse FC (+ out bias init role) ----------------
__global__ __launch_bounds__(256) void k_fcs2(const float* __restrict__ fw,
                                              const float* __restrict__ fb,
                                              const float* __restrict__ bsub,
                                              float* __restrict__ out,
                                              const float* __restrict__ ob) {
    int tid = threadIdx.x;
    if (blockIdx.x < 2048) {
        int wid = tid >> 5, lane = tid & 31;
        int grp = blockIdx.x * 2 + (wid >> 2);
        int b0 = (wid & 3) * 4;
        int cnt = g_idxcnt[grp];
        const int* idx = g_idxbuf + grp * 1024;
        const float* pk = g_wpk + grp * 768;
        const float* wb = fw + (size_t)grp * 6144;
        float acc[6][4];
#pragma unroll
        for (int r = 0; r < 6; r++)
#pragma unroll
            for (int b = 0; b < 4; b++) acc[r][b] = 0.f;
        int cend = min(cnt, 128);
        for (int k = lane; k < cend; k += 32) {
            int g = idx[k];
            float bs = bsub[g];
            float xv[4];
#pragma unroll
            for (int b = 0; b < 4; b++) xv[b] = lrelu(g_xcat[(b0 + b) * G_SZ + g] + bs, 0.01f);
#pragma unroll
            for (int r = 0; r < 6; r++) {
                float wv = pk[r * 128 + k];
#pragma unroll
                for (int b = 0; b < 4; b++) acc[r][b] += wv * xv[b];
            }
        }
        if (cnt > 128) {                         // paranoia path; statistically never taken
            for (int k = 128 + lane; k < cnt; k += 32) {
                int g = idx[k];
                float bs = bsub[g];
                float xv[4];
#pragma unroll
                for (int b = 0; b < 4; b++) xv[b] = lrelu(g_xcat[(b0 + b) * G_SZ + g] + bs, 0.01f);
#pragma unroll
                for (int r = 0; r < 6; r++) {
                    float wv = wb[r * 1024 + g];
#pragma unroll
                    for (int b = 0; b < 4; b++) acc[r][b] += wv * xv[b];
                }
            }
        }
#pragma unroll
        for (int r = 0; r < 6; r++) {
#pragma unroll
            for (int b = 0; b < 4; b++) {
                float v = acc[r][b];
#pragma unroll
                for (int o = 16; o; o >>= 1) v += __shfl_xor_sync(0xffffffffu, v, o);
                if (lane == 0) {
                    int j = grp * 6 + r;
                    int d = j >> 12, n = j & 4095;
                    g_h[n * 96 + (b0 + b) * 6 + d] = lrelu(v + fb[j], 0.01f);
                }
            }
        }
    } else {
        for (int i = tid; i < 512; i += 256) out[i] = ob[i & 31];
    }
}

// ---------------- L3: GAT projection ----------------
__global__ void k_mid(const float* __restrict__ gw, const float* __restrict__ gatt) {
    int tid = threadIdx.x;
    __shared__ float sgw[48], satt[16];
    if (tid < 48) sgw[tid] = gw[tid];
    if (tid < 16) satt[tid] = gatt[tid];
    __syncthreads();
    int gid = blockIdx.x * 256 + tid;             // n*16 + b
    const float2* hp = (const float2*)(g_h + gid * 6);
    float2 h01 = hp[0], h23 = hp[1], h45 = hp[2];
    float h6[6] = {h01.x, h01.y, h23.x, h23.y, h45.x, h45.y};
    float hn8[8];
#pragma unroll
    for (int k = 0; k < 8; k++) {
        float s = 0.f;
#pragma unroll
        for (int d = 0; d < 6; d++) s += h6[d] * sgw[d * 8 + k];
        hn8[k] = s;
    }
    float4* hnp = (float4*)(g_hn + gid * 8);
    hnp[0] = make_float4(hn8[0], hn8[1], hn8[2], hn8[3]);
    hnp[1] = make_float4(hn8[4], hn8[5], hn8[6], hn8[7]);
    float2 si, sj;
    si.x = hn8[0]*satt[0] + hn8[1]*satt[1] + hn8[2]*satt[2] + hn8[3]*satt[3];
    sj.x = hn8[0]*satt[4] + hn8[1]*satt[5] + hn8[2]*satt[6] + hn8[3]*satt[7];
    si.y = hn8[4]*satt[8] + hn8[5]*satt[9] + hn8[6]*satt[10] + hn8[7]*satt[11];
    sj.y = hn8[4]*satt[12] + hn8[5]*satt[13] + hn8[6]*satt[14] + hn8[7]*satt[15];
    ((float2*)g_si)[gid] = si;
    ((float2*)g_sj)[gid] = sj;
}

// ---------------- L4 (PROFILED): warp-per-dst GAT, uniform-broadcast index loads ----
__global__ __launch_bounds__(256) void k_gat(const float* __restrict__ gbias) {
    int tid = threadIdx.x;
    int wid = tid >> 5, lane = tid & 31;
    int n = blockIdx.x * 8 + wid;
    int deg = min(g_cnt[n], BKT_CAP);
    const int* __restrict__ bkt = g_bkt + n * BKT_CAP;
    float si = g_si[n * 32 + lane];
    float b0c = gbias[0], b1c = gbias[1], b2c = gbias[2], b3c = gbias[3];

    float wsum = 0.f;
    float a0 = 0.f, a1 = 0.f, a2 = 0.f, a3 = 0.f;
    int j = 0;
    for (; j + 3 < deg; j += 4) {
        // uniform loads: same address across warp -> L1 broadcast, no shfl chain
        int s0 = bkt[j], s1 = bkt[j + 1], s2 = bkt[j + 2], s3 = bkt[j + 3];
        float t0 = g_sj[s0 * 32 + lane];
        float t1 = g_sj[s1 * 32 + lane];
        float t2 = g_sj[s2 * 32 + lane];
        float t3 = g_sj[s3 * 32 + lane];
        float4 h0 = *(const float4*)(g_hn + s0 * 128 + lane * 4);
        float4 h1 = *(const float4*)(g_hn + s1 * 128 + lane * 4);
        float4 h2 = *(const float4*)(g_hn + s2 * 128 + lane * 4);
        float4 h3 = *(const float4*)(g_hn + s3 * 128 + lane * 4);
        float q0 = si + t0, q1 = si + t1, q2 = si + t2, q3 = si + t3;
        q0 = q0 >= 0.f ? q0 : 0.2f * q0;  q1 = q1 >= 0.f ? q1 : 0.2f * q1;
        q2 = q2 >= 0.f ? q2 : 0.2f * q2;  q3 = q3 >= 0.f ? q3 : 0.2f * q3;
        q0 = fminf(fmaxf(q0, -30.f), 30.f); q1 = fminf(fmaxf(q1, -30.f), 30.f);
        q2 = fminf(fmaxf(q2, -30.f), 30.f); q3 = fminf(fmaxf(q3, -30.f), 30.f);
        float w0 = __expf(q0), w1 = __expf(q1), w2 = __expf(q2), w3 = __expf(q3);
        wsum += (w0 + w1) + (w2 + w3);
        a0 += w0 * h0.x + w1 * h1.x + w2 * h2.x + w3 * h3.x;
        a1 += w0 * h0.y + w1 * h1.y + w2 * h2.y + w3 * h3.y;
        a2 += w0 * h0.z + w1 * h1.z + w2 * h2.z + w3 * h3.z;
        a3 += w0 * h0.w + w1 * h1.w + w2 * h2.w + w3 * h3.w;
    }
    for (; j < deg; j++) {
        int s = bkt[j];
        float q = si + g_sj[s * 32 + lane];
        q = q >= 0.f ? q : 0.2f * q;
        q = fminf(fmaxf(q, -30.f), 30.f);
        float w = __expf(q);
        wsum += w;
        float4 hv = *(const float4*)(g_hn + s * 128 + lane * 4);
        a0 += w * hv.x; a1 += w * hv.y; a2 += w * hv.z; a3 += w * hv.w;
    }
    float inv = (wsum > 0.f) ? 1.f / (wsum * (float)deg) : 0.f;
    a0 *= inv; a1 *= inv; a2 *= inv; a3 *= inv;
    // head mean: lanes (b*2) and (b*2+1) hold h=0,1
    float v0 = 0.5f * (a0 + __shfl_xor_sync(0xffffffffu, a0, 1)) + b0c;
    float v1 = 0.5f * (a1 + __shfl_xor_sync(0xffffffffu, a1, 1)) + b1c;
    float v2 = 0.5f * (a2 + __shfl_xor_sync(0xffffffffu, a2, 1)) + b2c;
    float v3 = 0.5f * (a3 + __shfl_xor_sync(0xffffffffu, a3, 1)) + b3c;
    if ((lane & 1) == 0) {
        int b = lane >> 1;
        float* op = g_o + b * 16384 + n;
        op[0]     = lrelu(v0, 0.01f);
        op[4096]  = lrelu(v1, 0.01f);
        op[8192]  = lrelu(v2, 0.01f);
        op[12288] = lrelu(v3, 0.01f);
    }
}

// ---------------- L5: readout, split x8 (+ cnt-zero and xcat-zero roles) ----------------
__global__ __launch_bounds__(256) void k_readout(const float* __restrict__ ow, float* __restrict__ out) {
    int k = blockIdx.x, sl = blockIdx.y;
    int tid = threadIdx.x;
    if (k == 32) {                                // zero g_cnt for next replay (sl<4 only)
        if (sl < 4) ((int4*)g_cnt)[sl * 256 + tid] = make_int4(0, 0, 0, 0);
        return;
    }
    if (k == 33) {                                // zero g_xcat for next replay
        if (sl < 8) {
            int i = sl * 512 + tid;
            ((float4*)g_xcat)[i] = make_float4(0.f, 0.f, 0.f, 0.f);
            ((float4*)g_xcat)[i + 256] = make_float4(0.f, 0.f, 0.f, 0.f);
        }
        return;
    }
    float acc[16];
#pragma unroll
    for (int b = 0; b < 16; b++) acc[b] = 0.f;
    const float* wk = ow + k * 16384 + sl * 2048;
    const float* op = g_o + sl * 2048;
#pragma unroll
    for (int it = 0; it < 8; it++) {
        int i = tid + it * 256;
        float w = wk[i];
#pragma unroll
        for (int b = 0; b < 16; b++) acc[b] += w * op[b * 16384 + i];
    }
    __shared__ float red[8][16];
    int lane = tid & 31, wid = tid >> 5;
#pragma unroll
    for (int b = 0; b < 16; b++) {
        float v = acc[b];
#pragma unroll
        for (int o = 16; o; o >>= 1) v += __shfl_xor_sync(0xffffffffu, v, o);
        if (lane == 0) red[wid][b] = v;
    }
    __syncthreads();
    if (tid < 16) {
        float s = 0.f;
#pragma unroll
        for (int w = 0; w < 8; w++) s += red[w][tid];
        atomicAdd(&out[tid * 32 + k], s);
    }
}

// ---------------- launch ----------------
extern "C" void kernel_launch(void* const* d_in, const int* in_sizes, int n_in,
                              void* d_out, int out_size) {
    const float* x    = (const float*)d_in[0];
    const int*   ei   = (const int*)  d_in[1];
    const float* Wsub = (const float*)d_in[2];
    const float* bsub = (const float*)d_in[3];
    const float* fw   = (const float*)d_in[4];
    const float* mr   = (const float*)d_in[5];
    const float* fb   = (const float*)d_in[6];
    const float* gw   = (const float*)d_in[7];
    const float* gatt = (const float*)d_in[8];
    const float* gb   = (const float*)d_in[9];
    const float* ow   = (const float*)d_in[10];
    const float* ob   = (const float*)d_in[11];
    float* out = (float*)d_out;

    k_main1<<<2624, 256>>>(x, Wsub, fw, mr, ei);   // 1: prep + bucket + subnet
    k_fcs2<<<2049, 256>>>(fw, fb, bsub, out, ob);  // 2: packed FC + out init
    k_mid<<<256, 256>>>(gw, gatt);                 // 3: proj
    k_gat<<<512, 256>>>(gb);                       // 4: <- PROFILED (broadcast-idx GAT)
    k_readout<<<dim3(34, 8), 256>>>(ow, out);      // 5: readout + cnt/xcat zero
}